// round 8
// baseline (speedup 1.0000x reference)
#include <cuda_runtime.h>
#include <cuda_bf16.h>

// FWHT, N = 4096, fp32, Sylvester ordering.
// e = r*256 + w*32 + lane  (r = bits 8-11, w = warp bits 5-7, lane = bits 0-4)
// Pass 1: fwht16 over r in registers (coalesced scalar load).
// Pass 2: 5 shfl.xor butterfly stages over the 5 lane bits.
// Pass 3: one smem exchange (identity layout, conflict-free both sides),
//         then 2x fwht8 over the 3 warp bits. Coalesced scalar store.
// L1 wavefronts/CTA: 128 (load) + 256 (smem) + 128 (store) = 512.

#define FWHT_N 4096

__global__ __launch_bounds__(256, 6)
void HadamardTransform_68891275428167_kernel(const float* __restrict__ x,
                                             float* __restrict__ y) {
    __shared__ float s[FWHT_N];          // 16 KB, identity layout s[e]

    const int t    = threadIdx.x;        // 0..255
    const int lane = t & 31;
    const size_t row_off = (size_t)blockIdx.x * FWHT_N;
    const float* __restrict__ xr = x + row_off;
    float* __restrict__ yr = y + row_off;

    float v[16];

    // ---- Load: v[r] = x[r*256 + t]; 16x LDG.32, 1 wf each. ----
#pragma unroll
    for (int r = 0; r < 16; r++)
        v[r] = xr[(r << 8) + t];

    // ---- Pass 1: fwht16 over r (bits 8-11). ----
#pragma unroll
    for (int h = 1; h < 16; h <<= 1) {
#pragma unroll
        for (int i = 0; i < 16; i++) {
            if ((i & h) == 0) {
                float a = v[i];
                float b = v[i + h];
                v[i]     = a + b;
                v[i + h] = a - b;
            }
        }
    }

    // ---- Pass 2: 5 shuffle-butterfly stages over lane bits 0-4. ----
    // bit=0 lane: own + partner;  bit=1 lane: partner - own.
#pragma unroll
    for (int h = 1; h <= 16; h <<= 1) {
        const float sgn = (lane & h) ? -1.0f : 1.0f;
#pragma unroll
        for (int i = 0; i < 16; i++) {
            float p = __shfl_xor_sync(0xffffffffu, v[i], h);
            v[i] = fmaf(sgn, v[i], p);
        }
    }

    // ---- Exchange: s[e] identity; both sides lane-consecutive. ----
#pragma unroll
    for (int r = 0; r < 16; r++)
        s[(r << 8) + t] = v[r];
    __syncthreads();

    // Read: reg q = (w<<1)|r0 holds e = ((wp*2+r0)<<8) + (w<<5) + lane,
    // where wp = t>>5. Lanes consecutive -> conflict-free.
    {
        const int wp = t >> 5;
#pragma unroll
        for (int q = 0; q < 16; q++) {
            const int r = (wp << 1) | (q & 1);
            const int w = q >> 1;
            v[q] = s[(r << 8) + (w << 5) + lane];
        }
    }

    // ---- Pass 3: fwht8 over w (q bits 1-3) for both r0 groups. ----
#pragma unroll
    for (int h = 2; h < 16; h <<= 1) {
#pragma unroll
        for (int i = 0; i < 16; i++) {
            if ((i & h) == 0) {
                float a = v[i];
                float b = v[i + h];
                v[i]     = a + b;
                v[i + h] = a - b;
            }
        }
    }

    // ---- Store: same e mapping as the read; 16x STG.32, 1 wf each. ----
    {
        const int wp = t >> 5;
#pragma unroll
        for (int q = 0; q < 16; q++) {
            const int r = (wp << 1) | (q & 1);
            const int w = q >> 1;
            yr[(r << 8) + (w << 5) + lane] = v[q];
        }
    }
}

extern "C" void kernel_launch(void* const* d_in, const int* in_sizes, int n_in,
                              void* d_out, int out_size) {
    const float* x = (const float*)d_in[0];
    float* y = (float*)d_out;

    const int rows = in_sizes[0] / FWHT_N;   // 16384
    HadamardTransform_68891275428167_kernel<<<rows, 256>>>(x, y);
}